// round 14
// baseline (speedup 1.0000x reference)
#include <cuda_runtime.h>
#include <math.h>

#define B_DIM 256
#define V_DIM 50257
#define BIN_FLOATS 50264              // V_DIM + max pad(3), rounded to /4
#define BIN_SMEM (BIN_FLOATS * 4)     // 201,056 B -> 1 CTA/SM
#define HALF_B 128

// Per-row 1/sum(exp), produced by bin_rows, consumed by transpose.
__device__ float g_inv[B_DIM];

// ---------------------------------------------------------------------------
// Bin kernel: self-normalizing smem binning, one CTA per row (b = bid + row0).
// Computes the row's softmax scatter AND publishes 1/rowsum to g_inv[b]
// (so no separate stats kernel / extra 51MB w read is needed).
// Vectorized: float4/int4 loads, LDS.128+STG.128 writeout via pad trick.
// ---------------------------------------------------------------------------
__global__ __launch_bounds__(1024)
void bin_rows(const int*   __restrict__ idx,
              const float* __restrict__ w,
              float*       __restrict__ avg,
              int row0) {
    extern __shared__ float bins[];     // BIN_FLOATS floats
    const int b = blockIdx.x + row0;
    const size_t rowoff = (size_t)b * V_DIM;
    const int pad = (int)(rowoff & 3);        // alignment phase of this row
    const int j0  = (4 - pad) & 3;            // first vec4-aligned element
    const int n4  = (V_DIM - j0) >> 2;        // full float4 groups
    const int tail0 = j0 + (n4 << 2);

    {   // zero the padded table (float4)
        float4* b4 = (float4*)bins;
        const float4 z = make_float4(0.f, 0.f, 0.f, 0.f);
        for (int j = threadIdx.x; j < BIN_FLOATS / 4; j += 1024) b4[j] = z;
    }
    __syncthreads();

    float s = 0.0f;

    if (threadIdx.x < j0) {                   // scalar head (0..3)
        const float e = __expf(__ldcs(w + rowoff + threadIdx.x));
        s += e;
        atomicAdd(&bins[__ldcs(idx + rowoff + threadIdx.x) + pad], e);
    }

    const float4* w4 = (const float4*)(w + rowoff + j0);
    const int4*   i4 = (const int4*)(idx + rowoff + j0);
    for (int i = threadIdx.x; i < n4; i += 1024) {
        const float4 x  = __ldcs(w4 + i);
        const int4   id = __ldcs(i4 + i);
        const float e0 = __expf(x.x), e1 = __expf(x.y);
        const float e2 = __expf(x.z), e3 = __expf(x.w);
        s += (e0 + e1) + (e2 + e3);
        atomicAdd(&bins[id.x + pad], e0);
        atomicAdd(&bins[id.y + pad], e1);
        atomicAdd(&bins[id.z + pad], e2);
        atomicAdd(&bins[id.w + pad], e3);
    }

    for (int j = tail0 + threadIdx.x; j < V_DIM; j += 1024) {  // scalar tail
        const float e = __expf(__ldcs(w + rowoff + j));
        s += e;
        atomicAdd(&bins[__ldcs(idx + rowoff + j) + pad], e);
    }

    // block-reduce the row sum; publish 1/sum
    #pragma unroll
    for (int o = 16; o > 0; o >>= 1)
        s += __shfl_xor_sync(0xFFFFFFFFu, s, o);
    __shared__ float ssum[32];
    const int lane = threadIdx.x & 31;
    const int wid  = threadIdx.x >> 5;
    if (lane == 0) ssum[wid] = s;
    __syncthreads();
    __shared__ float sinv;
    if (wid == 0) {
        float t = ssum[lane];               // exactly 32 warps
        #pragma unroll
        for (int o = 16; o > 0; o >>= 1)
            t += __shfl_xor_sync(0xFFFFFFFFu, t, o);
        if (lane == 0) {
            const float iv = 1.0f / t;
            sinv = iv;
            g_inv[b] = iv;                  // publish for transpose
        }
    }
    __syncthreads();
    const float inv = sinv;

    // writeout (16B-aligned body on smem and global)
    if (threadIdx.x < j0)
        __stcs(&avg[rowoff + threadIdx.x], bins[threadIdx.x + pad] * inv);

    const float4* bv = (const float4*)(bins + j0 + pad);
    float4*       ov = (float4*)(avg + rowoff + j0);
    for (int i = threadIdx.x; i < n4; i += 1024) {
        float4 o = bv[i];
        o.x *= inv; o.y *= inv; o.z *= inv; o.w *= inv;
        __stcs(ov + i, o);
    }

    for (int j = tail0 + threadIdx.x; j < V_DIM; j += 1024)
        __stcs(&avg[rowoff + j], bins[j + pad] * inv);
}

// ---------------------------------------------------------------------------
// Transpose kernel: pure streaming, rows [bt0*32, (bt0+4)*32).
// 32b x 128v tiles, XOR-swizzled float4 smem tile, conflict-free both phases.
// inv comes from g_inv (published by bin_rows for these rows already).
// ---------------------------------------------------------------------------
__global__ __launch_bounds__(1024)
void transpose_half(const float* __restrict__ w,
                    float*       __restrict__ wT,
                    int bt0) {
    __shared__ float4 tile[32][32];

    const int vt = blockIdx.x;
    const int bt = blockIdx.y + bt0;
    const int tx = threadIdx.x;
    const int ty = threadIdx.y;

    const int b = bt * 32 + ty;
    const size_t rowoff = (size_t)b * V_DIM;
    const float inv = __ldg(&g_inv[b]);

    const int vbase = vt * 128 + tx * 4;
    float4 wv;
    if (vbase + 3 < V_DIM) {
        float x[4];
        #pragma unroll
        for (int k = 0; k < 4; k++) x[k] = __ldg(w + rowoff + vbase + k);
        #pragma unroll
        for (int k = 0; k < 4; k++) ((float*)&wv)[k] = __expf(x[k]) * inv;
    } else {
        #pragma unroll
        for (int k = 0; k < 4; k++) {
            const int v = vbase + k;
            ((float*)&wv)[k] = (v < V_DIM) ? __expf(__ldg(w + rowoff + v)) * inv : 0.0f;
        }
    }
    tile[ty][tx ^ (ty >> 2)] = wv;
    __syncthreads();

    const int t = ty * 32 + tx;
    const int r = t >> 3;
    const int c = t & 7;
    const int v = vt * 128 + r;
    if (v < V_DIM) {
        const int wq  = r >> 2;
        const int sub = r & 3;
        float4 o;
        #pragma unroll
        for (int j = 0; j < 4; j++)
            ((float*)&o)[j] = ((const float*)&tile[c * 4 + j][wq ^ c])[sub];
        __stcs((float4*)&wT[(size_t)v * B_DIM + bt * 32 + c * 4], o);
    }
}

// ---------------------------------------------------------------------------
extern "C" void kernel_launch(void* const* d_in, const int* in_sizes, int n_in,
                              void* d_out, int out_size) {
    const int*   indices = (const int*)d_in[0];
    const float* w_es    = (const float*)d_in[1];

    float* avg = (float*)d_out;                           // [B, V]
    float* wT  = (float*)d_out + (size_t)B_DIM * V_DIM;   // [V, B]

    cudaStream_t s2;
    cudaEvent_t  eF, e1, e2;
    cudaStreamCreateWithFlags(&s2, cudaStreamNonBlocking);
    cudaEventCreateWithFlags(&eF, cudaEventDisableTiming);
    cudaEventCreateWithFlags(&e1, cudaEventDisableTiming);
    cudaEventCreateWithFlags(&e2, cudaEventDisableTiming);
    cudaFuncSetAttribute(bin_rows, cudaFuncAttributeMaxDynamicSharedMemorySize,
                         BIN_SMEM);

    // Fork: bin pipeline on s2, two 128-row halves (one full wave each).
    cudaEventRecord(eF, 0);
    cudaStreamWaitEvent(s2, eF, 0);
    bin_rows<<<HALF_B, 1024, BIN_SMEM, s2>>>(indices, w_es, avg, 0);
    cudaEventRecord(e1, s2);
    bin_rows<<<HALF_B, 1024, BIN_SMEM, s2>>>(indices, w_es, avg, HALF_B);
    cudaEventRecord(e2, s2);

    // Main stream: transpose halves gated on the bin halves that produce
    // their g_inv values. Transpose half 1 overlaps bin half 2.
    dim3 tgrid((V_DIM + 127) / 128, 4);   // 393 x 4 (128 rows)
    dim3 tblock(32, 32);
    cudaStreamWaitEvent(0, e1, 0);
    transpose_half<<<tgrid, tblock>>>(w_es, wT, 0);
    cudaStreamWaitEvent(0, e2, 0);
    transpose_half<<<tgrid, tblock>>>(w_es, wT, 4);
}

// round 16
// speedup vs baseline: 1.0670x; 1.0670x over previous
#include <cuda_runtime.h>
#include <math.h>

#define B_DIM 256
#define V_DIM 50257
#define BIN_FLOATS 50264              // V_DIM + max pad(3), rounded to /4
#define BIN_SMEM (BIN_FLOATS * 4)     // 201,056 B -> 1 CTA/SM
#define BIN_A 148                     // first bin launch: exactly one full wave
#define VT256 ((V_DIM + 255) / 256)   // 197 v-tiles of 256

// Per-row 1/sum(exp), produced by bin_rows, consumed by transpose.
__device__ float g_inv[B_DIM];

// ---------------------------------------------------------------------------
// Bin kernel: self-normalizing smem binning, one CTA per row.
// Publishes 1/rowsum to g_inv[b]; fully writes avg row (no zero pass needed).
// ---------------------------------------------------------------------------
__global__ __launch_bounds__(1024)
void bin_rows(const int*   __restrict__ idx,
              const float* __restrict__ w,
              float*       __restrict__ avg,
              int row0) {
    extern __shared__ float bins[];     // BIN_FLOATS floats
    const int b = blockIdx.x + row0;
    const size_t rowoff = (size_t)b * V_DIM;
    const int pad = (int)(rowoff & 3);
    const int j0  = (4 - pad) & 3;
    const int n4  = (V_DIM - j0) >> 2;
    const int tail0 = j0 + (n4 << 2);

    {   // zero the padded table (float4)
        float4* b4 = (float4*)bins;
        const float4 z = make_float4(0.f, 0.f, 0.f, 0.f);
        for (int j = threadIdx.x; j < BIN_FLOATS / 4; j += 1024) b4[j] = z;
    }
    __syncthreads();

    float s = 0.0f;

    if (threadIdx.x < j0) {                   // scalar head (0..3)
        const float e = __expf(__ldcs(w + rowoff + threadIdx.x));
        s += e;
        atomicAdd(&bins[__ldcs(idx + rowoff + threadIdx.x) + pad], e);
    }

    const float4* w4 = (const float4*)(w + rowoff + j0);
    const int4*   i4 = (const int4*)(idx + rowoff + j0);
    for (int i = threadIdx.x; i < n4; i += 1024) {
        const float4 x  = __ldcs(w4 + i);
        const int4   id = __ldcs(i4 + i);
        const float e0 = __expf(x.x), e1 = __expf(x.y);
        const float e2 = __expf(x.z), e3 = __expf(x.w);
        s += (e0 + e1) + (e2 + e3);
        atomicAdd(&bins[id.x + pad], e0);
        atomicAdd(&bins[id.y + pad], e1);
        atomicAdd(&bins[id.z + pad], e2);
        atomicAdd(&bins[id.w + pad], e3);
    }

    for (int j = tail0 + threadIdx.x; j < V_DIM; j += 1024) {  // scalar tail
        const float e = __expf(__ldcs(w + rowoff + j));
        s += e;
        atomicAdd(&bins[__ldcs(idx + rowoff + j) + pad], e);
    }

    // block-reduce the row sum; publish 1/sum
    #pragma unroll
    for (int o = 16; o > 0; o >>= 1)
        s += __shfl_xor_sync(0xFFFFFFFFu, s, o);
    __shared__ float ssum[32];
    const int lane = threadIdx.x & 31;
    const int wid  = threadIdx.x >> 5;
    if (lane == 0) ssum[wid] = s;
    __syncthreads();
    __shared__ float sinv;
    if (wid == 0) {
        float t = ssum[lane];
        #pragma unroll
        for (int o = 16; o > 0; o >>= 1)
            t += __shfl_xor_sync(0xFFFFFFFFu, t, o);
        if (lane == 0) {
            const float iv = 1.0f / t;
            sinv = iv;
            g_inv[b] = iv;
        }
    }
    __syncthreads();
    const float inv = sinv;

    // writeout (16B-aligned body on smem and global)
    if (threadIdx.x < j0)
        __stcs(&avg[rowoff + threadIdx.x], bins[threadIdx.x + pad] * inv);

    const float4* bv = (const float4*)(bins + j0 + pad);
    float4*       ov = (float4*)(avg + rowoff + j0);
    for (int i = threadIdx.x; i < n4; i += 1024) {
        float4 o = bv[i];
        o.x *= inv; o.y *= inv; o.z *= inv; o.w *= inv;
        __stcs(ov + i, o);
    }

    for (int j = tail0 + threadIdx.x; j < V_DIM; j += 1024)
        __stcs(&avg[rowoff + j], bins[j + pad] * inv);
}

// ---------------------------------------------------------------------------
// Transpose kernel: 32b x 256v tiles, 8 elems/thread, XOR-swizzled smem,
// conflict-free in both phases.
// ---------------------------------------------------------------------------
__global__ __launch_bounds__(1024)
void transpose_half(const float* __restrict__ w,
                    float*       __restrict__ wT,
                    int bt0) {
    __shared__ float4 tile[32][64];

    const int vt = blockIdx.x;
    const int bt = blockIdx.y + bt0;
    const int tx = threadIdx.x;
    const int ty = threadIdx.y;

    const int b = bt * 32 + ty;
    const size_t rowoff = (size_t)b * V_DIM;
    const float inv = __ldg(&g_inv[b]);
    const int q = ty >> 2;

    #pragma unroll
    for (int k = 0; k < 2; k++) {
        const int vbase = vt * 256 + k * 128 + tx * 4;
        float4 wv;
        if (vbase + 3 < V_DIM) {
            float x[4];
            #pragma unroll
            for (int j = 0; j < 4; j++) x[j] = __ldg(w + rowoff + vbase + j);
            #pragma unroll
            for (int j = 0; j < 4; j++) ((float*)&wv)[j] = __expf(x[j]) * inv;
        } else {
            #pragma unroll
            for (int j = 0; j < 4; j++) {
                const int v = vbase + j;
                ((float*)&wv)[j] = (v < V_DIM) ? __expf(__ldg(w + rowoff + v)) * inv : 0.0f;
            }
        }
        tile[ty][(k * 32 + tx) ^ q] = wv;
    }
    __syncthreads();

    const int t = ty * 32 + tx;
    #pragma unroll
    for (int kk = 0; kk < 2; kk++) {
        const int tt = t + kk * 1024;
        const int r = tt >> 3;          // v-local 0..255
        const int c = tt & 7;           // b-quad 0..7
        const int v = vt * 256 + r;
        if (v < V_DIM) {
            const int g   = r >> 2;
            const int sub = r & 3;
            float4 o;
            #pragma unroll
            for (int j = 0; j < 4; j++)
                ((float*)&o)[j] = ((const float*)&tile[c * 4 + j][g ^ c])[sub];
            __stcs((float4*)&wT[(size_t)v * B_DIM + bt * 32 + c * 4], o);
        }
    }
}

// ---------------------------------------------------------------------------
extern "C" void kernel_launch(void* const* d_in, const int* in_sizes, int n_in,
                              void* d_out, int out_size) {
    const int*   indices = (const int*)d_in[0];
    const float* w_es    = (const float*)d_in[1];

    float* avg = (float*)d_out;                           // [B, V]
    float* wT  = (float*)d_out + (size_t)B_DIM * V_DIM;   // [V, B]

    // Streams/events created EXACTLY ONCE (first call = pre-capture
    // correctness run), so their backing allocations are part of the
    // harness's pre-capture baseline and nothing is allocated during
    // capture or replay.
    struct Ctx {
        cudaStream_t s2, s3;
        cudaEvent_t  eF, eA, eB;
        Ctx() {
            cudaStreamCreateWithFlags(&s2, cudaStreamNonBlocking);
            cudaStreamCreateWithFlags(&s3, cudaStreamNonBlocking);
            cudaEventCreateWithFlags(&eF, cudaEventDisableTiming);
            cudaEventCreateWithFlags(&eA, cudaEventDisableTiming);
            cudaEventCreateWithFlags(&eB, cudaEventDisableTiming);
            cudaFuncSetAttribute(bin_rows,
                cudaFuncAttributeMaxDynamicSharedMemorySize, BIN_SMEM);
        }
    };
    static Ctx ctx;

    // Fork both bin halves at t=0 on separate streams.
    // binA = 148 rows (exactly wave 1 -> earliest possible event),
    // binB = 108 rows (wave 2).
    cudaEventRecord(ctx.eF, 0);
    cudaStreamWaitEvent(ctx.s2, ctx.eF, 0);
    cudaStreamWaitEvent(ctx.s3, ctx.eF, 0);
    bin_rows<<<BIN_A, 1024, BIN_SMEM, ctx.s2>>>(indices, w_es, avg, 0);
    cudaEventRecord(ctx.eA, ctx.s2);
    bin_rows<<<B_DIM - BIN_A, 1024, BIN_SMEM, ctx.s3>>>(indices, w_es, avg, BIN_A);
    cudaEventRecord(ctx.eB, ctx.s3);

    // Transpose chunk A: rows 0..127 (needs binA only) - overlaps binB.
    dim3 tgrid(VT256, 4);
    dim3 tblock(32, 32);
    cudaStreamWaitEvent(0, ctx.eA, 0);
    transpose_half<<<tgrid, tblock>>>(w_es, wT, 0);

    // Transpose chunk B: rows 128..255 (needs binA rows 128-147 + binB).
    cudaStreamWaitEvent(0, ctx.eB, 0);
    transpose_half<<<tgrid, tblock>>>(w_es, wT, 4);
}